// round 7
// baseline (speedup 1.0000x reference)
#include <cuda_runtime.h>
#include <cuda_bf16.h>
#include <math.h>
#include <stdint.h>

// Problem constants
#define Bsz  4
#define Lseq 4096
#define DIMc 1024
#define Hn   16
#define DHc  64
#define NFc  64
#define Mrows (Bsz * Lseq)          // 16384
#define BHc   (Bsz * Hn)            // 64
#define EPSf  1e-6f
#define QSCALE 32000.0f

// ---------------------------------------------------------------------------
// Scratch (device globals)
// ---------------------------------------------------------------------------
__device__ float g_q[(size_t)Mrows * DIMc];     // q, later reused as ctx
__device__ float g_k[(size_t)Mrows * DIMc];
__device__ float g_v[(size_t)Mrows * DIMc];
__device__ float g_phi[(size_t)BHc * Lseq * NFc];
__device__ float g_Nt[BHc * DHc * NFc];   // transposed: [bh][d][f]
__device__ float g_D[BHc * NFc];
__device__ float g_scale[8];              // 0=x, 1..4=Wq..Wo, 5=ctx

// int8 split buffers
__device__ char g_x8h[(size_t)Mrows * DIMc];   // x hi, later ctx hi
__device__ char g_x8l[(size_t)Mrows * DIMc];
__device__ char g_w8h[4 * DIMc * DIMc];
__device__ char g_w8l[4 * DIMc * DIMc];

// ---------------------------------------------------------------------------
// PTX helpers
// ---------------------------------------------------------------------------
__device__ __forceinline__ uint32_t smem_u32(const void* p) {
    uint32_t a;
    asm("{ .reg .u64 t; cvta.to.shared.u64 t, %1; cvt.u32.u64 %0, t; }" : "=r"(a) : "l"(p));
    return a;
}

#define CP16(dst, src) \
    asm volatile("cp.async.cg.shared.global [%0], [%1], 16;" :: "r"(dst), "l"(src))
#define CP_COMMIT() asm volatile("cp.async.commit_group;" ::: "memory")
#define CP_WAIT(n)  asm volatile("cp.async.wait_group %0;" :: "n"(n) : "memory")

__device__ __forceinline__ void ldsm_x4(uint32_t* r, uint32_t addr) {
    asm volatile("ldmatrix.sync.aligned.m8n8.x4.shared.b16 {%0,%1,%2,%3}, [%4];"
        : "=r"(r[0]), "=r"(r[1]), "=r"(r[2]), "=r"(r[3]) : "r"(addr));
}
__device__ __forceinline__ void imma16832(int* c, const uint32_t* a, const uint32_t* b) {
    asm volatile(
        "mma.sync.aligned.m16n8k32.row.col.s32.s8.s8.s32 "
        "{%0,%1,%2,%3}, {%4,%5,%6,%7}, {%8,%9}, {%0,%1,%2,%3};"
        : "+r"(c[0]), "+r"(c[1]), "+r"(c[2]), "+r"(c[3])
        : "r"(a[0]), "r"(a[1]), "r"(a[2]), "r"(a[3]), "r"(b[0]), "r"(b[1]));
}

// SMEM geometry: int8 rows of 64 bytes padded to 80 -> ldmatrix octets hit
// banks {0,20,8,28,16,4,24,12} (x4 bytes) : conflict-free.
#define ROWB8      80
#define MAT8       (128 * ROWB8)         // 10240
#define STG8       (4 * MAT8)            // 40960 : Ahi|Alo|Bhi|Blo
#define NST8       3
#define GEMM8_SMEM (1024 + NST8 * STG8)  // 123904
#define OFF8_AHI 0
#define OFF8_ALO MAT8
#define OFF8_BHI (2 * MAT8)
#define OFF8_BLO (3 * MAT8)

struct GemmArgs8 {
    const char* whi[3];
    const char* wlo[3];
    const float* bias[3];
    float* C[3];
    int wscale[3];
    int ascale;
};

// ---------------------------------------------------------------------------
// Init: zero accumulators + scales
// ---------------------------------------------------------------------------
__global__ void init_kernel() {
    int i = blockIdx.x * blockDim.x + threadIdx.x;
    if (i < BHc * DHc * NFc) g_Nt[i] = 0.0f;
    if (i < BHc * NFc)       g_D[i] = 0.0f;
    if (i < 8)               g_scale[i] = 0.0f;
}

// ---------------------------------------------------------------------------
// absmax reduction (atomicMax on positive-float bits)
// ---------------------------------------------------------------------------
__global__ void __launch_bounds__(256) absmax_kernel(const float* __restrict__ src,
                                                     int n4, float* out) {
    int i = blockIdx.x * blockDim.x + threadIdx.x;
    int stride = gridDim.x * blockDim.x;
    float m = 0.f;
    for (int j = i; j < n4; j += stride) {
        float4 v = ((const float4*)src)[j];
        m = fmaxf(m, fmaxf(fmaxf(fabsf(v.x), fabsf(v.y)),
                           fmaxf(fabsf(v.z), fabsf(v.w))));
    }
    #pragma unroll
    for (int o = 16; o > 0; o >>= 1)
        m = fmaxf(m, __shfl_xor_sync(0xffffffffu, m, o));
    __shared__ float wm[8];
    if ((threadIdx.x & 31) == 0) wm[threadIdx.x >> 5] = m;
    __syncthreads();
    if (threadIdx.x == 0) {
        float mm = wm[0];
        #pragma unroll
        for (int w = 1; w < 8; w++) mm = fmaxf(mm, wm[w]);
        atomicMax((int*)out, __float_as_int(mm));
    }
}

// ---------------------------------------------------------------------------
// fp32 -> int16 fixed-point split into two int8 planes
// ---------------------------------------------------------------------------
__global__ void __launch_bounds__(256) quant_kernel(const float* __restrict__ src,
                                                    const float* __restrict__ sp,
                                                    char* __restrict__ hi,
                                                    char* __restrict__ lo, int n4) {
    int i = blockIdx.x * blockDim.x + threadIdx.x;
    if (i >= n4) return;
    float inv = QSCALE / sp[0];
    float4 v = ((const float4*)src)[i];
    char h[4], l[4];
    float vv[4] = {v.x, v.y, v.z, v.w};
    #pragma unroll
    for (int e = 0; e < 4; e++) {
        int qv = __float2int_rn(vv[e] * inv);
        int l8 = (int)(signed char)(qv & 0xFF);
        int h8 = (qv - l8) >> 8;
        h[e] = (char)h8;
        l[e] = (char)l8;
    }
    ((uint*)hi)[i] = *(uint*)h;
    ((uint*)lo)[i] = *(uint*)l;
}

// ---------------------------------------------------------------------------
// IMMA s8-split GEMM: C = (s_A s_W/32000^2)(65536*hh + 256*(hl+lh)) + bias
// 128x128 tile, BK=64, 3-stage cp.async, 8 warps 2x4, warp tile 64x32.
// ---------------------------------------------------------------------------
__device__ __forceinline__ void issue_chunk8(
    uint32_t sbase, int t,
    const char* __restrict__ Ahi, const char* __restrict__ Alo,
    const char* __restrict__ Whi, const char* __restrict__ Wlo,
    int bm, int nLoc, int kOff)
{
    // 2048 16B segments: 512 per matrix (128 rows x 4 segs)
    #pragma unroll
    for (int j = 0; j < 8; j++) {
        int idx = t + j * 256;
        int r = idx >> 2, c = idx & 3;
        int rr = r & 127;
        uint32_t so;
        const char* src;
        if (r < 128)      { so = OFF8_AHI; src = Ahi + (size_t)(bm + rr) * DIMc; }
        else if (r < 256) { so = OFF8_ALO; src = Alo + (size_t)(bm + rr) * DIMc; }
        else if (r < 384) { so = OFF8_BHI; src = Whi + (size_t)(nLoc + rr) * DIMc; }
        else              { so = OFF8_BLO; src = Wlo + (size_t)(nLoc + rr) * DIMc; }
        CP16(sbase + so + (uint32_t)(rr * ROWB8 + c * 16), src + kOff + c * 16);
    }
    CP_COMMIT();
}

__global__ void __launch_bounds__(256, 1) gemm_s8(
    const char* __restrict__ Ahi, const char* __restrict__ Alo,
    GemmArgs8 args)
{
    extern __shared__ __align__(16) char sm[];
    float* sbias = (float*)sm;
    uint32_t sb = smem_u32(sm) + 1024;

    int t = threadIdx.x;
    int wid = t >> 5, lane = t & 31;
    int warp_m = wid >> 2, warp_n = wid & 3;
    int bm = blockIdx.y << 7;
    int wsel = blockIdx.x >> 3;
    int nLoc = (blockIdx.x & 7) << 7;

    const char* Whi = args.whi[wsel];
    const char* Wlo = args.wlo[wsel];
    float* C = args.C[wsel];

    if (t < 128) sbias[t] = args.bias[wsel][nLoc + t];
    float sf = g_scale[args.ascale] * g_scale[args.wscale[wsel]]
             * (1.0f / (QSCALE * QSCALE));

    int acc1[4][4][4];   // hh
    int acc2[4][4][4];   // hl + lh
    #pragma unroll
    for (int mi = 0; mi < 4; mi++)
        #pragma unroll
        for (int ni = 0; ni < 4; ni++)
            #pragma unroll
            for (int e = 0; e < 4; e++) { acc1[mi][ni][e] = 0; acc2[mi][ni][e] = 0; }

    uint32_t aoff = (uint32_t)((warp_m * 64 + (lane & 15)) * ROWB8 + (lane >> 4) * 16);
    uint32_t bpair = (uint32_t)((warp_n * 32 + (lane >> 4) * 8 + (lane & 7)) * ROWB8
                                + ((lane >> 3) & 1) * 16);

    issue_chunk8(sb + 0 * STG8, t, Ahi, Alo, Whi, Wlo, bm, nLoc, 0);
    issue_chunk8(sb + 1 * STG8, t, Ahi, Alo, Whi, Wlo, bm, nLoc, 64);

    #pragma unroll 1
    for (int ch = 0; ch < 16; ch++) {
        CP_WAIT(1);
        __syncthreads();
        if (ch + 2 < 16)
            issue_chunk8(sb + ((ch + 2) % NST8) * STG8, t,
                         Ahi, Alo, Whi, Wlo, bm, nLoc, (ch + 2) * 64);
        uint32_t stg = sb + (ch % NST8) * STG8;
        #pragma unroll
        for (int ks = 0; ks < 2; ks++) {     // two 32-byte K segments
            uint32_t ahi[4][4], alo[4][4], bhi[4][2], blo[4][2];
            #pragma unroll
            for (int mi = 0; mi < 4; mi++) {
                uint32_t a = stg + aoff + (uint32_t)(mi * 16 * ROWB8 + ks * 32);
                ldsm_x4(ahi[mi], a + OFF8_AHI);
                ldsm_x4(alo[mi], a + OFF8_ALO);
            }
            #pragma unroll
            for (int pni = 0; pni < 4; pni += 2) {
                uint32_t tmp[4];
                uint32_t b = stg + bpair + (uint32_t)(pni * 8 * ROWB8 + ks * 32);
                ldsm_x4(tmp, b + OFF8_BHI);
                bhi[pni][0] = tmp[0]; bhi[pni][1] = tmp[1];
                bhi[pni + 1][0] = tmp[2]; bhi[pni + 1][1] = tmp[3];
                ldsm_x4(tmp, b + OFF8_BLO);
                blo[pni][0] = tmp[0]; blo[pni][1] = tmp[1];
                blo[pni + 1][0] = tmp[2]; blo[pni + 1][1] = tmp[3];
            }
            #pragma unroll
            for (int mi = 0; mi < 4; mi++)
                #pragma unroll
                for (int ni = 0; ni < 4; ni++) {
                    imma16832(acc1[mi][ni], ahi[mi], bhi[ni]);
                    imma16832(acc2[mi][ni], ahi[mi], blo[ni]);
                    imma16832(acc2[mi][ni], alo[mi], bhi[ni]);
                }
        }
        __syncthreads();
    }

    // epilogue: scale and add bias
    #pragma unroll
    for (int mi = 0; mi < 4; mi++) {
        int row0 = bm + warp_m * 64 + mi * 16 + (lane >> 2);
        #pragma unroll
        for (int ni = 0; ni < 4; ni++) {
            int col = warp_n * 32 + ni * 8 + (lane & 3) * 2;
            float b0 = sbias[col], b1 = sbias[col + 1];
            float2 o0, o1;
            o0.x = sf * (65536.f * (float)acc1[mi][ni][0] + 256.f * (float)acc2[mi][ni][0]) + b0;
            o0.y = sf * (65536.f * (float)acc1[mi][ni][1] + 256.f * (float)acc2[mi][ni][1]) + b1;
            o1.x = sf * (65536.f * (float)acc1[mi][ni][2] + 256.f * (float)acc2[mi][ni][2]) + b0;
            o1.y = sf * (65536.f * (float)acc1[mi][ni][3] + 256.f * (float)acc2[mi][ni][3]) + b1;
            *(float2*)(C + (size_t)row0 * DIMc + nLoc + col) = o0;
            *(float2*)(C + (size_t)(row0 + 8) * DIMc + nLoc + col) = o1;
        }
    }
}

// ---------------------------------------------------------------------------
// Fused feature kernel (as R5/R6)
// ---------------------------------------------------------------------------
#define W0P 68
#define FEAT_SMEM ((W0P * 64 + 4 * 64 * 64) * 4)   // 82,688 B

__global__ void __launch_bounds__(256) feature_kernel(const float* __restrict__ Wrf) {
    extern __shared__ float fs[];
    float* W0t = fs;
    float* ks  = fs + W0P * 64;
    float* qs  = ks + 4096;
    float* Vs  = qs + 4096;
    float* Es  = Vs + 4096;

    int bh = blockIdx.y;
    int b = bh >> 4, h = bh & 15;
    int l0 = blockIdx.x * 64;
    int t = threadIdx.x;

    for (int e = t; e < 4096; e += 256) {
        int d = e >> 6, f = e & 63;
        W0t[f * W0P + d] = Wrf[h * 4096 + e];
    }
    for (int e = t; e < 1024; e += 256) {
        int row = e >> 4, c4 = (e & 15) << 2;
        size_t g = (size_t)(b * Lseq + l0 + row) * DIMc + h * DHc + c4;
        *(float4*)(ks + row * 64 + c4) = *(const float4*)(g_k + g);
        *(float4*)(qs + row * 64 + c4) = *(const float4*)(g_q + g);
        *(float4*)(Vs + row * 64 + c4) = *(const float4*)(g_v + g);
    }
    __syncthreads();

    int warp = t >> 5, lane = t & 31;
    const float* w0p = W0t + lane * W0P;
    const float* w1p = W0t + (lane + 32) * W0P;

    #pragma unroll 1
    for (int r = 0; r < 8; r++) {
        int l = warp * 8 + r;
        const float* krow = ks + l * 64;
        const float* qrow = qs + l * 64;
        float aK0 = 0.f, aK1 = 0.f, aQ0 = 0.f, aQ1 = 0.f, kk = 0.f;
        #pragma unroll
        for (int d = 0; d < 64; d += 4) {
            float4 kv = *(const float4*)(krow + d);
            float4 qv = *(const float4*)(qrow + d);
            float4 w0 = *(const float4*)(w0p + d);
            float4 w1 = *(const float4*)(w1p + d);
            aK0 = fmaf(kv.x, w0.x, aK0); aK0 = fmaf(kv.y, w0.y, aK0);
            aK0 = fmaf(kv.z, w0.z, aK0); aK0 = fmaf(kv.w, w0.w, aK0);
            aK1 = fmaf(kv.x, w1.x, aK1); aK1 = fmaf(kv.y, w1.y, aK1);
            aK1 = fmaf(kv.z, w1.z, aK1); aK1 = fmaf(kv.w, w1.w, aK1);
            aQ0 = fmaf(qv.x, w0.x, aQ0); aQ0 = fmaf(qv.y, w0.y, aQ0);
            aQ0 = fmaf(qv.z, w0.z, aQ0); aQ0 = fmaf(qv.w, w0.w, aQ0);
            aQ1 = fmaf(qv.x, w1.x, aQ1); aQ1 = fmaf(qv.y, w1.y, aQ1);
            aQ1 = fmaf(qv.z, w1.z, aQ1); aQ1 = fmaf(qv.w, w1.w, aQ1);
            kk  = fmaf(kv.x, kv.x, kk);  kk  = fmaf(kv.y, kv.y, kk);
            kk  = fmaf(kv.z, kv.z, kk);  kk  = fmaf(kv.w, kv.w, kk);
        }
        float hk = 0.5f * kk;
        Es[l * 64 + lane]      = __expf(aK0 - hk);
        Es[l * 64 + lane + 32] = __expf(aK1 - hk);

        float e0 = __expf(aQ0), e1 = __expf(aQ1);
        float s = e0 + e1;
        #pragma unroll
        for (int o = 16; o > 0; o >>= 1)
            s += __shfl_xor_sync(0xffffffffu, s, o);
        float inv = 1.0f / s;
        size_t base = ((size_t)bh * Lseq + l0 + l) * NFc;
        g_phi[base + lane]      = e0 * inv;
        g_phi[base + lane + 32] = e1 * inv;
    }
    __syncthreads();

    int tf = (t >> 4) << 2;
    int td = (t & 15) << 2;
    float acc[4][4];
    #pragma unroll
    for (int i = 0; i < 4; i++)
        #pragma unroll
        for (int j = 0; j < 4; j++) acc[i][j] = 0.0f;
    float dacc[4] = {0.f, 0.f, 0.f, 0.f};

    #pragma unroll 4
    for (int l = 0; l < 64; l++) {
        float4 a  = *(const float4*)(Es + l * 64 + tf);
        float4 b4 = *(const float4*)(Vs + l * 64 + td);
        float av[4] = {a.x, a.y, a.z, a.w};
        float bv[4] = {b4.x, b4.y, b4.z, b4.w};
        #pragma unroll
        for (int i = 0; i < 4; i++)
            #pragma unroll
            for (int j = 0; j < 4; j++)
                acc[i][j] = fmaf(av[i], bv[j], acc[i][j]);
        if (td == 0) {
            #pragma unroll
            for (int i = 0; i < 4; i++) dacc[i] += av[i];
        }
    }

    #pragma unroll
    for (int i = 0; i < 4; i++)
        #pragma unroll
        for (int j = 0; j < 4; j++)
            atomicAdd(&g_Nt[bh * (DHc * NFc) + (td + j) * NFc + tf + i], acc[i][j]);
    if (td == 0) {
        #pragma unroll
        for (int i = 0; i < 4; i++)
            atomicAdd(&g_D[bh * NFc + tf + i], dacc[i]);
    }
}

// ---------------------------------------------------------------------------
// Combine: ctx (fp32, into g_q) + fused absmax into g_scale[5]
// ---------------------------------------------------------------------------
__global__ void __launch_bounds__(256) combine_kernel() {
    int bh = blockIdx.y;
    int b = bh >> 4, h = bh & 15;
    int l0 = blockIdx.x * 64;

    __shared__ float Nts[64 * W0P];
    __shared__ float Ds[NFc];
    __shared__ float sSE;
    __shared__ float wmx[8];

    int t = threadIdx.x;
    for (int e = t; e < 4096; e += 256) {
        int d = e >> 6, f = e & 63;
        Nts[d * W0P + f] = g_Nt[bh * (DHc * NFc) + e];
    }
    if (t < NFc) Ds[t] = g_D[bh * NFc + t];
    __syncthreads();
    if (t == 0) {
        float s = 0.f;
        #pragma unroll
        for (int f = 0; f < NFc; f++) s += Ds[f];
        sSE = s * EPSf;
    }
    __syncthreads();

    int warp = t >> 5, lane = t & 31;
    const float* n0p = Nts + lane * W0P;
    const float* n1p = Nts + (lane + 32) * W0P;
    float lmax = 0.f;

    #pragma unroll 1
    for (int r = 0; r < 8; r++) {
        int l = l0 + warp * 8 + r;
        const float4* pr = (const float4*)(g_phi + ((size_t)bh * Lseq + l) * NFc);
        float num0 = 0.f, num1 = 0.f, den = 0.f;
        #pragma unroll
        for (int j = 0; j < 16; j++) {
            float4 p  = pr[j];
            float4 n0 = *(const float4*)(n0p + j * 4);
            float4 n1 = *(const float4*)(n1p + j * 4);
            float4 dd = *(const float4*)(Ds + j * 4);
            num0 = fmaf(p.x, n0.x, num0); num0 = fmaf(p.y, n0.y, num0);
            num0 = fmaf(p.z, n0.z, num0); num0 = fmaf(p.w, n0.w, num0);
            num1 = fmaf(p.x, n1.x, num1); num1 = fmaf(p.y, n1.y, num1);
            num1 = fmaf(p.z, n1.z, num1); num1 = fmaf(p.w, n1.w, num1);
            den  = fmaf(p.x, dd.x, den);  den  = fmaf(p.y, dd.y, den);
            den  = fmaf(p.z, dd.z, den);  den  = fmaf(p.w, dd.w, den);
        }
        float invd = 1.0f / (den + sSE);
        float v0 = num0 * invd;
        float v1 = num1 * invd;
        size_t g = (size_t)(b * Lseq + l) * DIMc + h * DHc;
        g_q[g + lane]      = v0;     // ctx reuses g_q
        g_q[g + lane + 32] = v1;
        lmax = fmaxf(lmax, fmaxf(fabsf(v0), fabsf(v1)));
    }

    #pragma unroll
    for (int o = 16; o > 0; o >>= 1)
        lmax = fmaxf(lmax, __shfl_xor_sync(0xffffffffu, lmax, o));
    if (lane == 0) wmx[warp] = lmax;
    __syncthreads();
    if (t == 0) {
        float m = wmx[0];
        #pragma unroll
        for (int i = 1; i < 8; i++) m = fmaxf(m, wmx[i]);
        atomicMax((int*)&g_scale[5], __float_as_int(m));
    }
}

// ---------------------------------------------------------------------------
// Launch
// ---------------------------------------------------------------------------
extern "C" void kernel_launch(void* const* d_in, const int* in_sizes, int n_in,
                              void* d_out, int out_size) {
    const float* x   = (const float*)d_in[0];
    const float* Wq  = (const float*)d_in[1];
    const float* bq  = (const float*)d_in[2];
    const float* Wk  = (const float*)d_in[3];
    const float* bk  = (const float*)d_in[4];
    const float* Wv  = (const float*)d_in[5];
    const float* bv  = (const float*)d_in[6];
    const float* Wo  = (const float*)d_in[7];
    const float* bo  = (const float*)d_in[8];
    const float* Wrf = (const float*)d_in[9];
    float* out = (float*)d_out;

    float *q, *k, *v, *scale;
    char *x8h, *x8l, *w8h, *w8l;
    cudaGetSymbolAddress((void**)&q,     g_q);
    cudaGetSymbolAddress((void**)&k,     g_k);
    cudaGetSymbolAddress((void**)&v,     g_v);
    cudaGetSymbolAddress((void**)&scale, g_scale);
    cudaGetSymbolAddress((void**)&x8h,   g_x8h);
    cudaGetSymbolAddress((void**)&x8l,   g_x8l);
    cudaGetSymbolAddress((void**)&w8h,   g_w8h);
    cudaGetSymbolAddress((void**)&w8l,   g_w8l);

    cudaFuncSetAttribute(gemm_s8, cudaFuncAttributeMaxDynamicSharedMemorySize, GEMM8_SMEM);
    cudaFuncSetAttribute(feature_kernel, cudaFuncAttributeMaxDynamicSharedMemorySize, FEAT_SMEM);

    const size_t WN = (size_t)DIMc * DIMc;     // 1M
    const int xn4 = (int)(((size_t)Mrows * DIMc) / 4);   // 4M
    const int wn4 = (int)(WN / 4);                       // 256K

    init_kernel<<<(BHc * DHc * NFc + 255) / 256, 256>>>();

    // absmax: x -> scale[0], Wq..Wo -> scale[1..4]
    absmax_kernel<<<1024, 256>>>(x,  xn4, scale + 0);
    absmax_kernel<<<256, 256>>>(Wq, wn4, scale + 1);
    absmax_kernel<<<256, 256>>>(Wk, wn4, scale + 2);
    absmax_kernel<<<256, 256>>>(Wv, wn4, scale + 3);
    absmax_kernel<<<256, 256>>>(Wo, wn4, scale + 4);

    // quantize
    quant_kernel<<<(xn4 + 255) / 256, 256>>>(x,  scale + 0, x8h, x8l, xn4);
    quant_kernel<<<(wn4 + 255) / 256, 256>>>(Wq, scale + 1, w8h + 0 * WN, w8l + 0 * WN, wn4);
    quant_kernel<<<(wn4 + 255) / 256, 256>>>(Wk, scale + 2, w8h + 1 * WN, w8l + 1 * WN, wn4);
    quant_kernel<<<(wn4 + 255) / 256, 256>>>(Wv, scale + 3, w8h + 2 * WN, w8l + 2 * WN, wn4);
    quant_kernel<<<(wn4 + 255) / 256, 256>>>(Wo, scale + 4, w8h + 3 * WN, w8l + 3 * WN, wn4);

    // Fused QKV GEMM: grid.x = 3 weights x 8 N-blocks
    {
        GemmArgs8 a;
        a.whi[0] = w8h + 0 * WN; a.whi[1] = w8h + 1 * WN; a.whi[2] = w8h + 2 * WN;
        a.wlo[0] = w8l + 0 * WN; a.wlo[1] = w8l + 1 * WN; a.wlo[2] = w8l + 2 * WN;
        a.bias[0] = bq; a.bias[1] = bk; a.bias[2] = bv;
        a.C[0] = q; a.C[1] = k; a.C[2] = v;
        a.wscale[0] = 1; a.wscale[1] = 2; a.wscale[2] = 3;
        a.ascale = 0;
        gemm_s8<<<dim3(24, Mrows / 128), 256, GEMM8_SMEM>>>(x8h, x8l, a);
    }

    feature_kernel<<<dim3(Lseq / 64, BHc), 256, FEAT_SMEM>>>(Wrf);
    combine_kernel<<<dim3(Lseq / 64, BHc), 256>>>();

    // quantize ctx (in g_q), reuse x8 buffers
    quant_kernel<<<(xn4 + 255) / 256, 256>>>(q, scale + 5, x8h, x8l, xn4);

    // Output GEMM
    {
        GemmArgs8 a;
        a.whi[0] = a.whi[1] = a.whi[2] = w8h + 3 * WN;
        a.wlo[0] = a.wlo[1] = a.wlo[2] = w8l + 3 * WN;
        a.bias[0] = a.bias[1] = a.bias[2] = bo;
        a.C[0] = a.C[1] = a.C[2] = out;
        a.wscale[0] = a.wscale[1] = a.wscale[2] = 4;
        a.ascale = 5;
        gemm_s8<<<dim3(8, Mrows / 128), 256, GEMM8_SMEM>>>(x8h, x8l, a);
    }
}

// round 8
// speedup vs baseline: 1.8822x; 1.8822x over previous
#include <cuda_runtime.h>
#include <cuda_bf16.h>
#include <math.h>
#include <stdint.h>

// Problem constants
#define Bsz  4
#define Lseq 4096
#define DIMc 1024
#define Hn   16
#define DHc  64
#define NFc  64
#define Mrows (Bsz * Lseq)          // 16384
#define BHc   (Bsz * Hn)            // 64
#define EPSf  1e-6f

// ---------------------------------------------------------------------------
// Scratch (device globals)
// ---------------------------------------------------------------------------
__device__ float g_q[(size_t)Mrows * DIMc];
__device__ float g_k[(size_t)Mrows * DIMc];
__device__ float g_v[(size_t)Mrows * DIMc];
__device__ float g_phi[(size_t)BHc * Lseq * NFc];
__device__ float g_Nt[BHc * DHc * NFc];   // transposed: [bh][d][f]
__device__ float g_D[BHc * NFc];

// bf16 split buffers
__device__ __nv_bfloat16 g_xhi[(size_t)Mrows * DIMc];
__device__ __nv_bfloat16 g_xlo[(size_t)Mrows * DIMc];
__device__ __nv_bfloat16 g_whi[4 * DIMc * DIMc];
__device__ __nv_bfloat16 g_wlo[4 * DIMc * DIMc];
__device__ __nv_bfloat16 g_chi[(size_t)Mrows * DIMc];
__device__ __nv_bfloat16 g_clo[(size_t)Mrows * DIMc];

// ---------------------------------------------------------------------------
// PTX helpers
// ---------------------------------------------------------------------------
__device__ __forceinline__ uint32_t smem_u32(const void* p) {
    uint32_t a;
    asm("{ .reg .u64 t; cvta.to.shared.u64 t, %1; cvt.u32.u64 %0, t; }" : "=r"(a) : "l"(p));
    return a;
}

#define CP16(dst, src) \
    asm volatile("cp.async.cg.shared.global [%0], [%1], 16;" :: "r"(dst), "l"(src))
#define CP_COMMIT() asm volatile("cp.async.commit_group;" ::: "memory")
#define CP_WAIT(n)  asm volatile("cp.async.wait_group %0;" :: "n"(n) : "memory")

__device__ __forceinline__ void ldsm_x4(uint32_t* r, uint32_t addr) {
    asm volatile("ldmatrix.sync.aligned.m8n8.x4.shared.b16 {%0,%1,%2,%3}, [%4];"
        : "=r"(r[0]), "=r"(r[1]), "=r"(r[2]), "=r"(r[3]) : "r"(addr));
}
__device__ __forceinline__ void mma16816(float* c, const uint32_t* a, const uint32_t* b) {
    asm volatile(
        "mma.sync.aligned.m16n8k16.row.col.f32.bf16.bf16.f32 "
        "{%0,%1,%2,%3}, {%4,%5,%6,%7}, {%8,%9}, {%0,%1,%2,%3};"
        : "+f"(c[0]), "+f"(c[1]), "+f"(c[2]), "+f"(c[3])
        : "r"(a[0]), "r"(a[1]), "r"(a[2]), "r"(a[3]), "r"(b[0]), "r"(b[1]));
}

// SMEM tile geometry: bf16 rows of 32 elems padded to 40 (80 bytes)
#define ROWB       80
#define A_BYTES    (128 * ROWB)          // 10240
#define B_BYTES    (256 * ROWB)          // 20480
#define STG_BYTES  (2 * A_BYTES + 2 * B_BYTES)   // 61440 : Ahi|Alo|Bhi|Blo
#define NSTAGE     3
#define GEMM_SMEM  (1024 + NSTAGE * STG_BYTES)   // 185344
#define OFF_AHI 0
#define OFF_ALO A_BYTES
#define OFF_BHI (2 * A_BYTES)
#define OFF_BLO (2 * A_BYTES + B_BYTES)

#define GTHREADS 512

struct GemmArgs {
    const __nv_bfloat16* whi[3];
    const __nv_bfloat16* wlo[3];
    const float* bias[3];
    float* C[3];
};

// ---------------------------------------------------------------------------
// fp32 -> bf16 hi/lo split
// ---------------------------------------------------------------------------
__global__ void split_kernel(const float* __restrict__ src,
                             __nv_bfloat16* __restrict__ hi,
                             __nv_bfloat16* __restrict__ lo, int n4) {
    int i = blockIdx.x * blockDim.x + threadIdx.x;
    if (i >= n4) return;
    float4 v = ((const float4*)src)[i];
    __nv_bfloat16 h[4], l[4];
    h[0] = __float2bfloat16(v.x); l[0] = __float2bfloat16(v.x - __bfloat162float(h[0]));
    h[1] = __float2bfloat16(v.y); l[1] = __float2bfloat16(v.y - __bfloat162float(h[1]));
    h[2] = __float2bfloat16(v.z); l[2] = __float2bfloat16(v.z - __bfloat162float(h[2]));
    h[3] = __float2bfloat16(v.w); l[3] = __float2bfloat16(v.w - __bfloat162float(h[3]));
    ((uint2*)hi)[i] = *(uint2*)h;
    ((uint2*)lo)[i] = *(uint2*)l;
}

// ---------------------------------------------------------------------------
// Init: zero N/D accumulators
// ---------------------------------------------------------------------------
__global__ void init_kernel() {
    int i = blockIdx.x * blockDim.x + threadIdx.x;
    if (i < BHc * DHc * NFc) g_Nt[i] = 0.0f;
    if (i < BHc * NFc)       g_D[i] = 0.0f;
}

// ---------------------------------------------------------------------------
// HMMA bf16-split GEMM: 128(M) x 256(N) tile, BK=32, 3-stage cp.async.
// 512 threads, 16 warps in 4x4: warp tile 32x64, 64 accum regs/thread.
// 4 warps per SMSP for latency hiding.
// ---------------------------------------------------------------------------
__device__ __forceinline__ void issue_chunk2(
    uint32_t sbase, int t,
    const __nv_bfloat16* __restrict__ Ahi, const __nv_bfloat16* __restrict__ Alo,
    const __nv_bfloat16* __restrict__ Whi, const __nv_bfloat16* __restrict__ Wlo,
    int bm, int nLoc, int kOff)
{
    // 3072 16B segments: A-hi 512, A-lo 512, B-hi 1024, B-lo 1024
    #pragma unroll
    for (int j = 0; j < 6; j++) {
        int idx = t + j * GTHREADS;
        int r = idx >> 2, c = idx & 3;
        uint32_t so;
        const __nv_bfloat16* src;
        if (r < 256) {        // A region
            int rr = r & 127;
            so = (uint32_t)((r < 128 ? OFF_AHI : OFF_ALO) + rr * ROWB + c * 16);
            src = (r < 128 ? Ahi : Alo) + (size_t)(bm + rr) * DIMc + kOff + c * 8;
        } else {              // B region
            int rb = r - 256;
            int rr = rb & 255;
            so = (uint32_t)((rb < 256 ? OFF_BHI : OFF_BLO) + rr * ROWB + c * 16);
            src = (rb < 256 ? Whi : Wlo) + (size_t)(nLoc + rr) * DIMc + kOff + c * 8;
        }
        CP16(sbase + so, src);
    }
    CP_COMMIT();
}

__global__ void __launch_bounds__(GTHREADS, 1) gemm_split(
    const __nv_bfloat16* __restrict__ Ahi, const __nv_bfloat16* __restrict__ Alo,
    GemmArgs args)
{
    extern __shared__ __align__(16) char sm[];
    float* sbias = (float*)sm;
    uint32_t sb = smem_u32(sm) + 1024;

    int t = threadIdx.x;
    int wid = t >> 5, lane = t & 31;
    int warp_m = wid >> 2, warp_n = wid & 3;   // 4x4 warp grid
    int bm = blockIdx.y << 7;
    int wsel = blockIdx.x >> 2;
    int nLoc = (blockIdx.x & 3) << 8;

    const __nv_bfloat16* Whi = args.whi[wsel];
    const __nv_bfloat16* Wlo = args.wlo[wsel];
    float* C = args.C[wsel];

    if (t < 256) sbias[t] = args.bias[wsel][nLoc + t];

    float acc[2][8][4];
    #pragma unroll
    for (int mi = 0; mi < 2; mi++)
        #pragma unroll
        for (int ni = 0; ni < 8; ni++)
            #pragma unroll
            for (int e = 0; e < 4; e++) acc[mi][ni][e] = 0.0f;

    uint32_t aoff = (uint32_t)((warp_m * 32 + (lane & 15)) * ROWB + (lane >> 4) * 16);
    uint32_t bpair = (uint32_t)((warp_n * 64 + (lane >> 4) * 8 + (lane & 7)) * ROWB
                                + ((lane >> 3) & 1) * 16);

    issue_chunk2(sb + 0 * STG_BYTES, t, Ahi, Alo, Whi, Wlo, bm, nLoc, 0);
    issue_chunk2(sb + 1 * STG_BYTES, t, Ahi, Alo, Whi, Wlo, bm, nLoc, 32);

    #pragma unroll 1
    for (int ch = 0; ch < 32; ch++) {
        CP_WAIT(1);
        __syncthreads();
        if (ch + 2 < 32)
            issue_chunk2(sb + ((ch + 2) % NSTAGE) * STG_BYTES, t,
                         Ahi, Alo, Whi, Wlo, bm, nLoc, (ch + 2) * 32);
        uint32_t stg = sb + (ch % NSTAGE) * STG_BYTES;
        #pragma unroll
        for (int ks = 0; ks < 2; ks++) {
            uint32_t ahi[2][4], alo[2][4], bhi[8][2], blo[8][2];
            #pragma unroll
            for (int mi = 0; mi < 2; mi++) {
                uint32_t a = stg + aoff + (uint32_t)(mi * 16 * ROWB + ks * 32);
                ldsm_x4(ahi[mi], a + OFF_AHI);
                ldsm_x4(alo[mi], a + OFF_ALO);
            }
            #pragma unroll
            for (int pni = 0; pni < 8; pni += 2) {
                uint32_t tmp[4];
                uint32_t b = stg + bpair + (uint32_t)(pni * 8 * ROWB + ks * 32);
                ldsm_x4(tmp, b + OFF_BHI);
                bhi[pni][0] = tmp[0]; bhi[pni][1] = tmp[1];
                bhi[pni + 1][0] = tmp[2]; bhi[pni + 1][1] = tmp[3];
                ldsm_x4(tmp, b + OFF_BLO);
                blo[pni][0] = tmp[0]; blo[pni][1] = tmp[1];
                blo[pni + 1][0] = tmp[2]; blo[pni + 1][1] = tmp[3];
            }
            #pragma unroll
            for (int mi = 0; mi < 2; mi++)
                #pragma unroll
                for (int ni = 0; ni < 8; ni++) {
                    mma16816(acc[mi][ni], ahi[mi], bhi[ni]);
                    mma16816(acc[mi][ni], ahi[mi], blo[ni]);
                    mma16816(acc[mi][ni], alo[mi], bhi[ni]);
                }
        }
        __syncthreads();
    }

    // epilogue
    #pragma unroll
    for (int mi = 0; mi < 2; mi++) {
        int row0 = bm + warp_m * 32 + mi * 16 + (lane >> 2);
        #pragma unroll
        for (int ni = 0; ni < 8; ni++) {
            int col = warp_n * 64 + ni * 8 + (lane & 3) * 2;
            float b0 = sbias[col], b1 = sbias[col + 1];
            float2 o0 = make_float2(acc[mi][ni][0] + b0, acc[mi][ni][1] + b1);
            float2 o1 = make_float2(acc[mi][ni][2] + b0, acc[mi][ni][3] + b1);
            *(float2*)(C + (size_t)row0 * DIMc + nLoc + col) = o0;
            *(float2*)(C + (size_t)(row0 + 8) * DIMc + nLoc + col) = o1;
        }
    }
}

// ---------------------------------------------------------------------------
// Fused feature kernel (proven R5 version)
// ---------------------------------------------------------------------------
#define W0P 68
#define FEAT_SMEM ((W0P * 64 + 4 * 64 * 64) * 4)   // 82,688 B

__global__ void __launch_bounds__(256) feature_kernel(const float* __restrict__ Wrf) {
    extern __shared__ float fs[];
    float* W0t = fs;
    float* ks  = fs + W0P * 64;
    float* qs  = ks + 4096;
    float* Vs  = qs + 4096;
    float* Es  = Vs + 4096;

    int bh = blockIdx.y;
    int b = bh >> 4, h = bh & 15;
    int l0 = blockIdx.x * 64;
    int t = threadIdx.x;

    for (int e = t; e < 4096; e += 256) {
        int d = e >> 6, f = e & 63;
        W0t[f * W0P + d] = Wrf[h * 4096 + e];
    }
    for (int e = t; e < 1024; e += 256) {
        int row = e >> 4, c4 = (e & 15) << 2;
        size_t g = (size_t)(b * Lseq + l0 + row) * DIMc + h * DHc + c4;
        *(float4*)(ks + row * 64 + c4) = *(const float4*)(g_k + g);
        *(float4*)(qs + row * 64 + c4) = *(const float4*)(g_q + g);
        *(float4*)(Vs + row * 64 + c4) = *(const float4*)(g_v + g);
    }
    __syncthreads();

    int warp = t >> 5, lane = t & 31;
    const float* w0p = W0t + lane * W0P;
    const float* w1p = W0t + (lane + 32) * W0P;

    #pragma unroll 1
    for (int r = 0; r < 8; r++) {
        int l = warp * 8 + r;
        const float* krow = ks + l * 64;
        const float* qrow = qs + l * 64;
        float aK0 = 0.f, aK1 = 0.f, aQ0 = 0.f, aQ1 = 0.f, kk = 0.f;
        #pragma unroll
        for (int d = 0; d < 64; d += 4) {
            float4 kv = *(const float4*)(krow + d);
            float4 qv = *(const float4*)(qrow + d);
            float4 w0 = *(const float4*)(w0p + d);
            float4 w1 = *(const float4*)(w1p + d);
            aK0 = fmaf(kv.x, w0.x, aK0); aK0 = fmaf(kv.y, w0.y, aK0);
            aK0 = fmaf(kv.z, w0.z, aK0); aK0 = fmaf(kv.w, w0.w, aK0);
            aK1 = fmaf(kv.x, w1.x, aK1); aK1 = fmaf(kv.y, w1.y, aK1);
            aK1 = fmaf(kv.z, w1.z, aK1); aK1 = fmaf(kv.w, w1.w, aK1);
            aQ0 = fmaf(qv.x, w0.x, aQ0); aQ0 = fmaf(qv.y, w0.y, aQ0);
            aQ0 = fmaf(qv.z, w0.z, aQ0); aQ0 = fmaf(qv.w, w0.w, aQ0);
            aQ1 = fmaf(qv.x, w1.x, aQ1); aQ1 = fmaf(qv.y, w1.y, aQ1);
            aQ1 = fmaf(qv.z, w1.z, aQ1); aQ1 = fmaf(qv.w, w1.w, aQ1);
            kk  = fmaf(kv.x, kv.x, kk);  kk  = fmaf(kv.y, kv.y, kk);
            kk  = fmaf(kv.z, kv.z, kk);  kk  = fmaf(kv.w, kv.w, kk);
        }
        float hk = 0.5f * kk;
        Es[l * 64 + lane]      = __expf(aK0 - hk);
        Es[l * 64 + lane + 32] = __expf(aK1 - hk);

        float e0 = __expf(aQ0), e1 = __expf(aQ1);
        float s = e0 + e1;
        #pragma unroll
        for (int o = 16; o > 0; o >>= 1)
            s += __shfl_xor_sync(0xffffffffu, s, o);
        float inv = 1.0f / s;
        size_t base = ((size_t)bh * Lseq + l0 + l) * NFc;
        g_phi[base + lane]      = e0 * inv;
        g_phi[base + lane + 32] = e1 * inv;
    }
    __syncthreads();

    int tf = (t >> 4) << 2;
    int td = (t & 15) << 2;
    float acc[4][4];
    #pragma unroll
    for (int i = 0; i < 4; i++)
        #pragma unroll
        for (int j = 0; j < 4; j++) acc[i][j] = 0.0f;
    float dacc[4] = {0.f, 0.f, 0.f, 0.f};

    #pragma unroll 4
    for (int l = 0; l < 64; l++) {
        float4 a  = *(const float4*)(Es + l * 64 + tf);
        float4 b4 = *(const float4*)(Vs + l * 64 + td);
        float av[4] = {a.x, a.y, a.z, a.w};
        float bv[4] = {b4.x, b4.y, b4.z, b4.w};
        #pragma unroll
        for (int i = 0; i < 4; i++)
            #pragma unroll
            for (int j = 0; j < 4; j++)
                acc[i][j] = fmaf(av[i], bv[j], acc[i][j]);
        if (td == 0) {
            #pragma unroll
            for (int i = 0; i < 4; i++) dacc[i] += av[i];
        }
    }

    #pragma unroll
    for (int i = 0; i < 4; i++)
        #pragma unroll
        for (int j = 0; j < 4; j++)
            atomicAdd(&g_Nt[bh * (DHc * NFc) + (td + j) * NFc + tf + i], acc[i][j]);
    if (td == 0) {
        #pragma unroll
        for (int i = 0; i < 4; i++)
            atomicAdd(&g_D[bh * NFc + tf + i], dacc[i]);
    }
}

// ---------------------------------------------------------------------------
// Combine (proven R5 version)
// ---------------------------------------------------------------------------
__global__ void __launch_bounds__(256) combine_kernel() {
    int bh = blockIdx.y;
    int b = bh >> 4, h = bh & 15;
    int l0 = blockIdx.x * 64;

    __shared__ float Nts[64 * W0P];
    __shared__ float Ds[NFc];
    __shared__ float sSE;

    int t = threadIdx.x;
    for (int e = t; e < 4096; e += 256) {
        int d = e >> 6, f = e & 63;
        Nts[d * W0P + f] = g_Nt[bh * (DHc * NFc) + e];
    }
    if (t < NFc) Ds[t] = g_D[bh * NFc + t];
    __syncthreads();
    if (t == 0) {
        float s = 0.f;
        #pragma unroll
        for (int f = 0; f < NFc; f++) s += Ds[f];
        sSE = s * EPSf;
    }
    __syncthreads();

    int warp = t >> 5, lane = t & 31;
    const float* n0p = Nts + lane * W0P;
    const float* n1p = Nts + (lane + 32) * W0P;

    #pragma unroll 1
    for (int r = 0; r < 8; r++) {
        int l = l0 + warp * 8 + r;
        const float4* pr = (const float4*)(g_phi + ((size_t)bh * Lseq + l) * NFc);
        float num0 = 0.f, num1 = 0.f, den = 0.f;
        #pragma unroll
        for (int j = 0; j < 16; j++) {
            float4 p  = pr[j];
            float4 n0 = *(const float4*)(n0p + j * 4);
            float4 n1 = *(const float4*)(n1p + j * 4);
            float4 dd = *(const float4*)(Ds + j * 4);
            num0 = fmaf(p.x, n0.x, num0); num0 = fmaf(p.y, n0.y, num0);
            num0 = fmaf(p.z, n0.z, num0); num0 = fmaf(p.w, n0.w, num0);
            num1 = fmaf(p.x, n1.x, num1); num1 = fmaf(p.y, n1.y, num1);
            num1 = fmaf(p.z, n1.z, num1); num1 = fmaf(p.w, n1.w, num1);
            den  = fmaf(p.x, dd.x, den);  den  = fmaf(p.y, dd.y, den);
            den  = fmaf(p.z, dd.z, den);  den  = fmaf(p.w, dd.w, den);
        }
        float invd = 1.0f / (den + sSE);
        float v0 = num0 * invd;
        float v1 = num1 * invd;
        size_t g = (size_t)(b * Lseq + l) * DIMc + h * DHc;
        __nv_bfloat16 h0 = __float2bfloat16(v0);
        __nv_bfloat16 h1 = __float2bfloat16(v1);
        g_chi[g + lane]      = h0;
        g_chi[g + lane + 32] = h1;
        g_clo[g + lane]      = __float2bfloat16(v0 - __bfloat162float(h0));
        g_clo[g + lane + 32] = __float2bfloat16(v1 - __bfloat162float(h1));
    }
}

// ---------------------------------------------------------------------------
// Launch
// ---------------------------------------------------------------------------
extern "C" void kernel_launch(void* const* d_in, const int* in_sizes, int n_in,
                              void* d_out, int out_size) {
    const float* x   = (const float*)d_in[0];
    const float* Wq  = (const float*)d_in[1];
    const float* bq  = (const float*)d_in[2];
    const float* Wk  = (const float*)d_in[3];
    const float* bk  = (const float*)d_in[4];
    const float* Wv  = (const float*)d_in[5];
    const float* bv  = (const float*)d_in[6];
    const float* Wo  = (const float*)d_in[7];
    const float* bo  = (const float*)d_in[8];
    const float* Wrf = (const float*)d_in[9];
    float* out = (float*)d_out;

    float *q, *k, *v;
    __nv_bfloat16 *xhi, *xlo, *whi, *wlo, *chi, *clo;
    cudaGetSymbolAddress((void**)&q,   g_q);
    cudaGetSymbolAddress((void**)&k,   g_k);
    cudaGetSymbolAddress((void**)&v,   g_v);
    cudaGetSymbolAddress((void**)&xhi, g_xhi);
    cudaGetSymbolAddress((void**)&xlo, g_xlo);
    cudaGetSymbolAddress((void**)&whi, g_whi);
    cudaGetSymbolAddress((void**)&wlo, g_wlo);
    cudaGetSymbolAddress((void**)&chi, g_chi);
    cudaGetSymbolAddress((void**)&clo, g_clo);

    cudaFuncSetAttribute(gemm_split, cudaFuncAttributeMaxDynamicSharedMemorySize, GEMM_SMEM);
    cudaFuncSetAttribute(feature_kernel, cudaFuncAttributeMaxDynamicSharedMemorySize, FEAT_SMEM);

    const size_t WN = (size_t)DIMc * DIMc;
    {
        int n4 = (int)(((size_t)Mrows * DIMc) / 4);
        split_kernel<<<(n4 + 255) / 256, 256>>>(x, xhi, xlo, n4);
        int w4 = (int)(WN / 4);
        split_kernel<<<(w4 + 255) / 256, 256>>>(Wq, whi + 0 * WN, wlo + 0 * WN, w4);
        split_kernel<<<(w4 + 255) / 256, 256>>>(Wk, whi + 1 * WN, wlo + 1 * WN, w4);
        split_kernel<<<(w4 + 255) / 256, 256>>>(Wv, whi + 2 * WN, wlo + 2 * WN, w4);
        split_kernel<<<(w4 + 255) / 256, 256>>>(Wo, whi + 3 * WN, wlo + 3 * WN, w4);
    }

    init_kernel<<<(BHc * DHc * NFc + 255) / 256, 256>>>();

    // Fused QKV GEMM: grid.x = 3 weights x 4 N-blocks
    {
        GemmArgs a;
        a.whi[0] = whi + 0 * WN; a.whi[1] = whi + 1 * WN; a.whi[2] = whi + 2 * WN;
        a.wlo[0] = wlo + 0 * WN; a.wlo[1] = wlo + 1 * WN; a.wlo[2] = wlo + 2 * WN;
        a.bias[0] = bq; a.bias[1] = bk; a.bias[2] = bv;
        a.C[0] = q; a.C[1] = k; a.C[2] = v;
        gemm_split<<<dim3(12, Mrows / 128), GTHREADS, GEMM_SMEM>>>(xhi, xlo, a);
    }

    feature_kernel<<<dim3(Lseq / 64, BHc), 256, FEAT_SMEM>>>(Wrf);
    combine_kernel<<<dim3(Lseq / 64, BHc), 256>>>();

    // Output GEMM
    {
        GemmArgs a;
        a.whi[0] = a.whi[1] = a.whi[2] = whi + 3 * WN;
        a.wlo[0] = a.wlo[1] = a.wlo[2] = wlo + 3 * WN;
        a.bias[0] = a.bias[1] = a.bias[2] = bo;
        a.C[0] = a.C[1] = a.C[2] = out;
        gemm_split<<<dim3(4, Mrows / 128), GTHREADS, GEMM_SMEM>>>(chi, clo, a);
    }
}